// round 9
// baseline (speedup 1.0000x reference)
#include <cuda_runtime.h>
#include <cstdint>

// ---------------- problem constants ----------------
#define NPTS   1000000
#define FX     512
#define FY     512
#define FZ     64
#define FIN    64
#define FH     32
#define SCORE_T 0.1f
#define CENT_T  0.2f
#define MAXP    128
#define CCAP    2048
#define BIN1_BASE 0x3E4Cu      // float_bits(0.2) >> 16 ; peak scores in (0.2, 1.0)
#define NBIN1  512

// padded grid: [2][514][514][66], pad cells always 0
#define PX 514
#define PY 514
#define PZ 66
#define PCELLS (2*PX*PY*PZ)
#define DXS (PY*PZ)            // 33924
#define DYS (PZ)               // 66

// ---------------- device scratch (zero-init at module load) ----------------
__device__ __align__(16) unsigned int g_grid[PCELLS];
__device__ int                g_cell[NPTS];     // packed coords (b<<24|x<<15|y<<6|z)
__device__ int                g_touch[NPTS];    // padded cells with s>0.1 (to reset)
__device__ unsigned long long g_cand[NPTS];     // s>0.2 candidates: (sb<<32)|~idx
__device__ int                g_ccellp[NPTS];   // padded cell per candidate
__device__ unsigned long long g_keys[NPTS];     // peaks
__device__ unsigned long long g_ckeys[CCAP];    // threshold survivors
__device__ __align__(16) int  g_hist1[NBIN1];
__device__ int g_touch_count, g_cand_count, g_peak_count, g_ccount;
__device__ unsigned int g_thresh;

// ---------------- f32x2 helpers ----------------
__device__ __forceinline__ unsigned long long pk2(float x) {
    unsigned long long r; unsigned xi = __float_as_uint(x);
    asm("mov.b64 %0, {%1, %1};" : "=l"(r) : "r"(xi));
    return r;
}
__device__ __forceinline__ void fma2(unsigned long long& d, unsigned long long a, unsigned long long b) {
    asm("fma.rn.f32x2 %0, %1, %2, %0;" : "+l"(d) : "l"(a), "l"(b));
}
__device__ __forceinline__ float2 up2(unsigned long long v) {
    unsigned a, b;
    asm("mov.b64 {%0, %1}, %2;" : "=r"(a), "=r"(b) : "l"(v));
    return make_float2(__uint_as_float(a), __uint_as_float(b));
}

// ---------------- K A1: cleanup grid via prev replay's touch list ----------------
__global__ void __launch_bounds__(256) k_clean_grid()
{
    int tn  = g_touch_count;
    int gsz = gridDim.x * blockDim.x;
    for (int i = blockIdx.x * blockDim.x + threadIdx.x; i < tn; i += gsz)
        g_grid[g_touch[i]] = 0u;
}

// ---------------- K A2: clear hist ----------------
__global__ void __launch_bounds__(NBIN1) k_clean_hist()
{
    g_hist1[threadIdx.x] = 0;
}

// ---------------- K A3: reset counters ----------------
__global__ void k_reset()
{
    if (threadIdx.x == 0) {
        g_touch_count = 0; g_cand_count = 0; g_peak_count = 0; g_ccount = 0;
    }
}

// ---------------- K1 (4th launch -> ncu target): MLP ----------------
#define FPAD 33   // row pitch in floats for staged features (bank-conflict-free)

__global__ void __launch_bounds__(256) k_mlp(
    const float* __restrict__ feats,
    const int*   __restrict__ cb, const int* __restrict__ cx,
    const int*   __restrict__ cy, const int* __restrict__ cz,
    const int*   __restrict__ mask,
    const float* __restrict__ W1, const float* __restrict__ b1,
    const float* __restrict__ W2, const float* __restrict__ b2,
    float* __restrict__ out_score)
{
    __shared__ __align__(16) float sW1[FIN * FH];   // 8 KB
    __shared__ __align__(16) float sb1[FH];
    __shared__ float sW2[FH];
    __shared__ float sb2;
    __shared__ float sF[256 * FPAD];                // 33 KB staged features

    int t = threadIdx.x;
    for (int i = t; i < FIN * FH; i += 256) sW1[i] = W1[i];
    if (t < FH) { sb1[t] = b1[t]; sW2[t] = W2[t]; }
    if (t == 0) sb2 = b2[0];

    int blockBase = blockIdx.x * 256;
    int i = blockBase + t;
    bool valid = (i < NPTS);

    const float4* F4 = reinterpret_cast<const float4*>(feats);

    unsigned long long acc[FH / 2];
    const unsigned long long* b1p = reinterpret_cast<const unsigned long long*>(sb1);

    // ---- stage chunk 0: features 0..31 ----
    #pragma unroll
    for (int u = 0; u < 8; u++) {
        int lin = u * 256 + t;
        int p   = lin >> 3;
        int f4  = lin & 7;
        int gp  = blockBase + p; if (gp >= NPTS) gp = NPTS - 1;
        float4 v = F4[(size_t)gp * 16 + f4];
        float* dst = &sF[p * FPAD + f4 * 4];
        dst[0] = v.x; dst[1] = v.y; dst[2] = v.z; dst[3] = v.w;
    }
    __syncthreads();

    #pragma unroll
    for (int j = 0; j < FH / 2; j++) acc[j] = b1p[j];

    #pragma unroll 8
    for (int f = 0; f < 32; f++) {
        unsigned long long fp = pk2(sF[t * FPAD + f]);
        const ulonglong2* w = reinterpret_cast<const ulonglong2*>(&sW1[f * FH]);
        #pragma unroll
        for (int q = 0; q < FH / 4; q++) {
            ulonglong2 ww = w[q];
            fma2(acc[2 * q + 0], fp, ww.x);
            fma2(acc[2 * q + 1], fp, ww.y);
        }
    }
    __syncthreads();

    // ---- stage chunk 1: features 32..63 ----
    #pragma unroll
    for (int u = 0; u < 8; u++) {
        int lin = u * 256 + t;
        int p   = lin >> 3;
        int f4  = lin & 7;
        int gp  = blockBase + p; if (gp >= NPTS) gp = NPTS - 1;
        float4 v = F4[(size_t)gp * 16 + 8 + f4];
        float* dst = &sF[p * FPAD + f4 * 4];
        dst[0] = v.x; dst[1] = v.y; dst[2] = v.z; dst[3] = v.w;
    }
    __syncthreads();

    #pragma unroll 8
    for (int f = 0; f < 32; f++) {
        unsigned long long fp = pk2(sF[t * FPAD + f]);
        const ulonglong2* w = reinterpret_cast<const ulonglong2*>(&sW1[(f + 32) * FH]);
        #pragma unroll
        for (int q = 0; q < FH / 4; q++) {
            ulonglong2 ww = w[q];
            fma2(acc[2 * q + 0], fp, ww.x);
            fma2(acc[2 * q + 1], fp, ww.y);
        }
    }

    float z = sb2;
    #pragma unroll
    for (int j = 0; j < FH / 2; j++) {
        float2 a = up2(acc[j]);
        z = fmaf(fmaxf(a.x, 0.0f), sW2[2 * j],     z);
        z = fmaf(fmaxf(a.y, 0.0f), sW2[2 * j + 1], z);
    }

    // ---- epilogue ----
    float s = 0.0f;
    int cellp = 0;
    unsigned sb = 0u;
    if (valid) {
        s = 1.0f / (1.0f + expf(-z));
        if (mask[i] == 0) s = 0.0f;
        out_score[i] = s;
        int b = cb[i], x = cx[i], y = cy[i], zc = cz[i];
        g_cell[i] = (b << 24) | (x << 15) | (y << 6) | zc;
        cellp = ((b * PX + x + 1) * PY + y + 1) * PZ + (zc + 1);
        sb = __float_as_uint(s);
    }
    int lane = t & 31;

    bool dep = valid && (s > SCORE_T);
    if (dep) atomicMax(&g_grid[cellp], sb);
    unsigned m = __ballot_sync(0xFFFFFFFFu, dep);
    int base = 0;
    if (lane == 0 && m) base = atomicAdd(&g_touch_count, __popc(m));
    base = __shfl_sync(0xFFFFFFFFu, base, 0);
    if (dep) g_touch[base + __popc(m & ((1u << lane) - 1u))] = cellp;

    bool cnd = valid && (s > CENT_T);
    unsigned m2 = __ballot_sync(0xFFFFFFFFu, cnd);
    int base2 = 0;
    if (lane == 0 && m2) base2 = atomicAdd(&g_cand_count, __popc(m2));
    base2 = __shfl_sync(0xFFFFFFFFu, base2, 0);
    if (cnd) {
        int pos = base2 + __popc(m2 & ((1u << lane) - 1u));
        g_cand[pos]   = ((unsigned long long)sb << 32) | (unsigned)(~(unsigned)i);
        g_ccellp[pos] = cellp;
    }
}

// ---------------- K2: peak detect (2 loads per z-row) ----------------
__global__ void __launch_bounds__(256) k_peak()
{
    int n   = g_cand_count;
    int gsz = gridDim.x * blockDim.x;
    int idx = blockIdx.x * blockDim.x + threadIdx.x;
    int iters = (n + gsz - 1) / gsz;
    int lane = threadIdx.x & 31;

    for (int it = 0; it < iters; it++, idx += gsz) {
        bool valid = (idx < n);
        unsigned long long key = 0ULL;
        unsigned sb = 0u, hmax = 0u;
        if (valid) {
            key = g_cand[idx];
            sb  = (unsigned)(key >> 32);
            int cp = g_ccellp[idx];
            #pragma unroll
            for (int dx = -1; dx <= 1; dx++) {
                #pragma unroll
                for (int dy = -1; dy <= 1; dy++) {
                    int base = cp + dx * DXS + dy * DYS;
                    int al   = base & ~1;                       // 8B-aligned pair start
                    uint2 A  = *reinterpret_cast<const uint2*>(&g_grid[al]);
                    unsigned S = g_grid[al + ((base & 1) ? 2 : -1)];
                    unsigned mx = A.x > A.y ? A.x : A.y;
                    mx = S > mx ? S : mx;
                    hmax = mx > hmax ? mx : hmax;
                }
            }
        }
        bool isPeak = valid && (hmax == sb);
        unsigned m = __ballot_sync(0xFFFFFFFFu, isPeak);
        int base = 0;
        if (lane == 0 && m) base = atomicAdd(&g_peak_count, __popc(m));
        base = __shfl_sync(0xFFFFFFFFu, base, 0);
        if (isPeak) {
            g_keys[base + __popc(m & ((1u << lane) - 1u))] = key;
            atomicAdd(&g_hist1[(sb >> 16) - BIN1_BASE], 1);
        }
    }
}

// ---------------- K3: single-level threshold (1 block, 512 thr) ----------------
__global__ void __launch_bounds__(NBIN1) k_thresh()
{
    __shared__ int csum[NBIN1];
    int t = threadIdx.x;
    int h = g_hist1[t];
    csum[t] = h;
    __syncthreads();
    for (int off = 1; off < NBIN1; off <<= 1) {
        int v = (t >= off) ? csum[t - off] : 0;
        __syncthreads();
        csum[t] += v;
        __syncthreads();
    }
    int total = csum[NBIN1 - 1];
    if (total < MAXP) {
        if (t == 0) g_thresh = 0u;      // take all peaks
        return;
    }
    int above = total - csum[t];        // strictly above bin t
    if (above < MAXP && above + h >= MAXP)
        g_thresh = ((unsigned)(t + BIN1_BASE)) << 16;
}

// ---------------- K4: compact survivors (grid-wide) ----------------
__global__ void __launch_bounds__(256) k_compact()
{
    int n = g_peak_count;
    unsigned th = g_thresh;
    int gsz = gridDim.x * blockDim.x;
    int idx = blockIdx.x * blockDim.x + threadIdx.x;
    int iters = (n + gsz - 1) / gsz;
    int lane = threadIdx.x & 31;
    for (int it = 0; it < iters; it++, idx += gsz) {
        bool take = false;
        unsigned long long key = 0ULL;
        if (idx < n) {
            key = g_keys[idx];
            take = ((unsigned)(key >> 32) >= th);
        }
        unsigned m = __ballot_sync(0xFFFFFFFFu, take);
        int base = 0;
        if (lane == 0 && m) base = atomicAdd(&g_ccount, __popc(m));
        base = __shfl_sync(0xFFFFFFFFu, base, 0);
        if (take) {
            int pos = base + __popc(m & ((1u << lane) - 1u));
            if (pos < CCAP) g_ckeys[pos] = key;
        }
    }
}

// ---------------- K5: sort 2048 + emit outputs (1 block, 1024 thr) ----------------
__global__ void __launch_bounds__(1024) k_sortout(float* __restrict__ out)
{
    __shared__ unsigned long long sk[CCAP];     // 16 KB
    __shared__ int fill[MAXP];
    __shared__ int sValid;
    int t = threadIdx.x;
    int M = g_ccount; if (M > CCAP) M = CCAP;
    sk[t]        = (t        < M) ? g_ckeys[t]        : 0ULL;
    sk[t + 1024] = (t + 1024 < M) ? g_ckeys[t + 1024] : 0ULL;
    __syncthreads();

    // bitonic sort, descending (2048 elems, 2/thread)
    for (int kk = 2; kk <= CCAP; kk <<= 1) {
        for (int j = kk >> 1; j > 0; j >>= 1) {
            #pragma unroll
            for (int half = 0; half < 2; half++) {
                int i = t + half * 1024;
                int ixj = i ^ j;
                if (ixj > i) {
                    unsigned long long a = sk[i], b = sk[ixj];
                    bool desc = ((i & kk) == 0);
                    if (desc ? (a < b) : (a > b)) { sk[i] = b; sk[ixj] = a; }
                }
            }
            __syncthreads();
        }
    }

    if (t == 0) {
        int valid = M < MAXP ? M : MAXP;
        sValid = valid;
        if (valid < MAXP) {   // practically never taken
            int need = MAXP - valid, got = 0;
            for (int i = 0; i < NPTS && got < need; i++) {
                bool isP = false;
                for (int q = 0; q < valid; q++) {
                    int pidx = (int)(~(unsigned)(sk[q] & 0xFFFFFFFFu));
                    if (pidx == i) { isP = true; break; }
                }
                if (!isP) { fill[valid + got] = i; got++; }
            }
        }
    }
    __syncthreads();

    if (t < MAXP) {
        int valid = sValid;
        float sc; int idx;
        if (t < valid) {
            unsigned long long key = sk[t];
            sc  = __uint_as_float((unsigned)(key >> 32));
            idx = (int)(~(unsigned)(key & 0xFFFFFFFFu));
        } else {
            sc  = -1.0f;
            idx = fill[t];
        }
        out[NPTS + t]        = (float)idx;
        out[NPTS + MAXP + t] = sc;
        int cell = g_cell[idx];
        float* pc = out + NPTS + 2 * MAXP + (size_t)t * 4;
        pc[0] = (float)(cell >> 24);
        pc[1] = (float)((cell >> 15) & 511);
        pc[2] = (float)((cell >> 6) & 511);
        pc[3] = (float)(cell & 63);
    }
}

// ---------------- launch ----------------
extern "C" void kernel_launch(void* const* d_in, const int* in_sizes, int n_in,
                              void* d_out, int out_size) {
    const float* feats = (const float*)d_in[0];
    const int*   cb    = (const int*)  d_in[1];
    const int*   cx    = (const int*)  d_in[2];
    const int*   cy    = (const int*)  d_in[3];
    const int*   cz    = (const int*)  d_in[4];
    const int*   mask  = (const int*)  d_in[5];
    const float* W1    = (const float*)d_in[6];
    const float* b1    = (const float*)d_in[7];
    const float* W2    = (const float*)d_in[8];
    const float* b2    = (const float*)d_in[9];
    float* out = (float*)d_out;

    // cleanup of PREVIOUS replay's state runs first; no-op on the very first call.
    k_clean_grid<<<2048, 256>>>();
    k_clean_hist<<<1, NBIN1>>>();
    k_reset<<<1, 32>>>();
    k_mlp<<<(NPTS + 255) / 256, 256>>>(feats, cb, cx, cy, cz, mask,
                                       W1, b1, W2, b2, out);   // 4th launch -> ncu
    k_peak<<<2048, 256>>>();
    k_thresh<<<1, NBIN1>>>();
    k_compact<<<512, 256>>>();
    k_sortout<<<1, 1024>>>(out);
}

// round 11
// speedup vs baseline: 1.5644x; 1.5644x over previous
#include <cuda_runtime.h>
#include <cstdint>

// ---------------- problem constants ----------------
#define NPTS   1000000
#define FX     512
#define FY     512
#define FZ     64
#define FIN    64
#define FH     32
#define SCORE_T 0.1f
#define CENT_T  0.2f
#define MAXP    128
#define CCAP    2048
#define BIN1_BASE 0x3E4Cu      // float_bits(0.2) >> 16 ; peak scores in (0.2, 1.0)
#define NBIN1  512

// padded grid: [2][514][514][66], pad cells always 0
#define PX 514
#define PY 514
#define PZ 66
#define PCELLS (2*PX*PY*PZ)
#define DXS (PY*PZ)            // 33924
#define DYS (PZ)               // 66

// ---------------- device scratch (zero-init at module load) ----------------
__device__ __align__(16) unsigned int g_grid[PCELLS];
__device__ int                g_cell[NPTS];     // packed coords (b<<24|x<<15|y<<6|z)
__device__ int                g_touch[NPTS];    // padded cells with s>0.1 (to reset)
__device__ unsigned long long g_cand[NPTS];     // s>0.2 candidates: (sb<<32)|~idx
__device__ int                g_ccellp[NPTS];   // padded cell per candidate
__device__ unsigned long long g_keys[NPTS];     // peaks
__device__ unsigned long long g_ckeys[CCAP];    // threshold survivors
__device__ __align__(16) int  g_hist1[NBIN1];
__device__ int g_touch_count, g_cand_count, g_peak_count, g_ccount;
__device__ unsigned int g_thresh;

// ---------------- f32x2 helpers ----------------
__device__ __forceinline__ unsigned long long pk2(float x) {
    unsigned long long r; unsigned xi = __float_as_uint(x);
    asm("mov.b64 %0, {%1, %1};" : "=l"(r) : "r"(xi));
    return r;
}
__device__ __forceinline__ void fma2(unsigned long long& d, unsigned long long a, unsigned long long b) {
    asm("fma.rn.f32x2 %0, %1, %2, %0;" : "+l"(d) : "l"(a), "l"(b));
}
__device__ __forceinline__ float2 up2(unsigned long long v) {
    unsigned a, b;
    asm("mov.b64 {%0, %1}, %2;" : "=r"(a), "=r"(b) : "l"(v));
    return make_float2(__uint_as_float(a), __uint_as_float(b));
}

// ---------------- K A1: cleanup grid via prev replay's touch list ----------------
__global__ void __launch_bounds__(256) k_clean_grid()
{
    int tn  = g_touch_count;
    int gsz = gridDim.x * blockDim.x;
    for (int i = blockIdx.x * blockDim.x + threadIdx.x; i < tn; i += gsz)
        g_grid[g_touch[i]] = 0u;
}

// ---------------- K A2: clear hist ----------------
__global__ void __launch_bounds__(NBIN1) k_clean_hist()
{
    g_hist1[threadIdx.x] = 0;
}

// ---------------- K A3: reset counters ----------------
__global__ void k_reset()
{
    if (threadIdx.x == 0) {
        g_touch_count = 0; g_cand_count = 0; g_peak_count = 0; g_ccount = 0;
    }
}

// ---------------- K1 (4th launch -> ncu target): register-blocked GEMM MLP --------
// Block: 256 points x 32 hidden. Thread (tid = m_grp*8 + n_grp):
//   8 points (m_grp*8..+7) x 4 cols (n_grp*4..+3), acc as 16 x f32x2.
// Features staged per 32-feature chunk as float4, XOR-swizzled so the 4 m_grps
// of a warp hit distinct bank-quads; weight rows are 128B -> n_grp spans banks.
__global__ void __launch_bounds__(256) k_mlp(
    const float* __restrict__ feats,
    const int*   __restrict__ cb, const int* __restrict__ cx,
    const int*   __restrict__ cy, const int* __restrict__ cz,
    const int*   __restrict__ mask,
    const float* __restrict__ W1, const float* __restrict__ b1,
    const float* __restrict__ W2, const float* __restrict__ b2,
    float* __restrict__ out_score)
{
    __shared__ __align__(16) float4 sF4[256 * 8];   // 32 KB: one 32-feature chunk
    __shared__ __align__(16) float  sW1s[FIN * FH]; // 8 KB  [k][n]
    __shared__ __align__(16) float  sb1s[FH];
    __shared__ __align__(16) float  sW2s[FH];
    __shared__ float sb2s;

    int t = threadIdx.x;
    for (int i = t; i < FIN * FH; i += 256) sW1s[i] = W1[i];
    if (t < FH) { sb1s[t] = b1[t]; sW2s[t] = W2[t]; }
    if (t == 0) sb2s = b2[0];

    int blockBase = blockIdx.x * 256;
    int m_grp = t >> 3;            // 0..31
    int n_grp = t & 7;             // 0..7
    int sw    = 2 * (m_grp & 3);   // XOR swizzle for this thread's point rows

    const float4* F4 = reinterpret_cast<const float4*>(feats);

    // ---- stage chunk 0 (features 0..31) ----
    #pragma unroll
    for (int u = 0; u < 8; u++) {
        int lin = u * 256 + t;
        int p   = lin >> 3;
        int f4  = lin & 7;
        int gp  = blockBase + p; if (gp >= NPTS) gp = NPTS - 1;
        sF4[p * 8 + (f4 ^ (2 * ((p >> 3) & 3)))] = F4[(size_t)gp * 16 + f4];
    }
    __syncthreads();

    unsigned long long acc[16];
    {
        ulonglong2 binit = *reinterpret_cast<const ulonglong2*>(&sb1s[n_grp * 4]);
        #pragma unroll
        for (int pp = 0; pp < 8; pp++) { acc[2 * pp] = binit.x; acc[2 * pp + 1] = binit.y; }
    }

    // ---- consume chunk 0 ----
    #pragma unroll
    for (int k4 = 0; k4 < 8; k4++) {
        ulonglong2 w0 = *reinterpret_cast<const ulonglong2*>(&sW1s[(k4 * 4 + 0) * FH + n_grp * 4]);
        ulonglong2 w1 = *reinterpret_cast<const ulonglong2*>(&sW1s[(k4 * 4 + 1) * FH + n_grp * 4]);
        ulonglong2 w2 = *reinterpret_cast<const ulonglong2*>(&sW1s[(k4 * 4 + 2) * FH + n_grp * 4]);
        ulonglong2 w3 = *reinterpret_cast<const ulonglong2*>(&sW1s[(k4 * 4 + 3) * FH + n_grp * 4]);
        #pragma unroll
        for (int pp = 0; pp < 8; pp++) {
            float4 fv = sF4[(m_grp * 8 + pp) * 8 + (k4 ^ sw)];
            unsigned long long fp;
            fp = pk2(fv.x); fma2(acc[2*pp], fp, w0.x); fma2(acc[2*pp+1], fp, w0.y);
            fp = pk2(fv.y); fma2(acc[2*pp], fp, w1.x); fma2(acc[2*pp+1], fp, w1.y);
            fp = pk2(fv.z); fma2(acc[2*pp], fp, w2.x); fma2(acc[2*pp+1], fp, w2.y);
            fp = pk2(fv.w); fma2(acc[2*pp], fp, w3.x); fma2(acc[2*pp+1], fp, w3.y);
        }
    }
    __syncthreads();

    // ---- stage chunk 1 (features 32..63) ----
    #pragma unroll
    for (int u = 0; u < 8; u++) {
        int lin = u * 256 + t;
        int p   = lin >> 3;
        int f4  = lin & 7;
        int gp  = blockBase + p; if (gp >= NPTS) gp = NPTS - 1;
        sF4[p * 8 + (f4 ^ (2 * ((p >> 3) & 3)))] = F4[(size_t)gp * 16 + 8 + f4];
    }
    __syncthreads();

    // ---- consume chunk 1 ----
    #pragma unroll
    for (int k4 = 0; k4 < 8; k4++) {
        ulonglong2 w0 = *reinterpret_cast<const ulonglong2*>(&sW1s[(32 + k4 * 4 + 0) * FH + n_grp * 4]);
        ulonglong2 w1 = *reinterpret_cast<const ulonglong2*>(&sW1s[(32 + k4 * 4 + 1) * FH + n_grp * 4]);
        ulonglong2 w2 = *reinterpret_cast<const ulonglong2*>(&sW1s[(32 + k4 * 4 + 2) * FH + n_grp * 4]);
        ulonglong2 w3 = *reinterpret_cast<const ulonglong2*>(&sW1s[(32 + k4 * 4 + 3) * FH + n_grp * 4]);
        #pragma unroll
        for (int pp = 0; pp < 8; pp++) {
            float4 fv = sF4[(m_grp * 8 + pp) * 8 + (k4 ^ sw)];
            unsigned long long fp;
            fp = pk2(fv.x); fma2(acc[2*pp], fp, w0.x); fma2(acc[2*pp+1], fp, w0.y);
            fp = pk2(fv.y); fma2(acc[2*pp], fp, w1.x); fma2(acc[2*pp+1], fp, w1.y);
            fp = pk2(fv.z); fma2(acc[2*pp], fp, w2.x); fma2(acc[2*pp+1], fp, w2.y);
            fp = pk2(fv.w); fma2(acc[2*pp], fp, w3.x); fma2(acc[2*pp+1], fp, w3.y);
        }
    }

    // ---- second layer: per-thread partial over its 4 cols, butterfly over n_grp ----
    float4 w2v = *reinterpret_cast<const float4*>(&sW2s[n_grp * 4]);
    float part[8];
    #pragma unroll
    for (int pp = 0; pp < 8; pp++) {
        float2 a0 = up2(acc[2 * pp]);
        float2 a1 = up2(acc[2 * pp + 1]);
        float p0 = fmaxf(a0.x, 0.0f) * w2v.x;
        p0 = fmaf(fmaxf(a0.y, 0.0f), w2v.y, p0);
        p0 = fmaf(fmaxf(a1.x, 0.0f), w2v.z, p0);
        p0 = fmaf(fmaxf(a1.y, 0.0f), w2v.w, p0);
        part[pp] = p0;
    }
    #pragma unroll
    for (int off = 1; off < 8; off <<= 1) {
        #pragma unroll
        for (int pp = 0; pp < 8; pp++)
            part[pp] += __shfl_xor_sync(0xFFFFFFFFu, part[pp], off);
    }
    float z = part[n_grp] + sb2s;   // lane's point = blockBase + m_grp*8 + n_grp = blockBase + t

    // ---- epilogue (identical addressing to prior rounds) ----
    int i = blockBase + t;
    bool valid = (i < NPTS);
    float s = 0.0f;
    int cellp = 0;
    unsigned sb = 0u;
    if (valid) {
        s = 1.0f / (1.0f + expf(-z));
        if (mask[i] == 0) s = 0.0f;
        out_score[i] = s;
        int b = cb[i], x = cx[i], y = cy[i], zc = cz[i];
        g_cell[i] = (b << 24) | (x << 15) | (y << 6) | zc;
        cellp = ((b * PX + x + 1) * PY + y + 1) * PZ + (zc + 1);
        sb = __float_as_uint(s);
    }
    int lane = t & 31;

    bool dep = valid && (s > SCORE_T);
    if (dep) atomicMax(&g_grid[cellp], sb);
    unsigned m = __ballot_sync(0xFFFFFFFFu, dep);
    int base = 0;
    if (lane == 0 && m) base = atomicAdd(&g_touch_count, __popc(m));
    base = __shfl_sync(0xFFFFFFFFu, base, 0);
    if (dep) g_touch[base + __popc(m & ((1u << lane) - 1u))] = cellp;

    bool cnd = valid && (s > CENT_T);
    unsigned m2 = __ballot_sync(0xFFFFFFFFu, cnd);
    int base2 = 0;
    if (lane == 0 && m2) base2 = atomicAdd(&g_cand_count, __popc(m2));
    base2 = __shfl_sync(0xFFFFFFFFu, base2, 0);
    if (cnd) {
        int pos = base2 + __popc(m2 & ((1u << lane) - 1u));
        g_cand[pos]   = ((unsigned long long)sb << 32) | (unsigned)(~(unsigned)i);
        g_ccellp[pos] = cellp;
    }
}

// ---------------- K2: peak detect (simple 3-scalar-load rows) ----------------
__global__ void __launch_bounds__(256) k_peak()
{
    int n   = g_cand_count;
    int gsz = gridDim.x * blockDim.x;
    int idx = blockIdx.x * blockDim.x + threadIdx.x;
    int iters = (n + gsz - 1) / gsz;
    int lane = threadIdx.x & 31;

    for (int it = 0; it < iters; it++, idx += gsz) {
        bool valid = (idx < n);
        unsigned long long key = 0ULL;
        unsigned sb = 0u, hmax = 0u;
        if (valid) {
            key = g_cand[idx];
            sb  = (unsigned)(key >> 32);
            int cp = g_ccellp[idx];
            #pragma unroll
            for (int dx = -1; dx <= 1; dx++) {
                #pragma unroll
                for (int dy = -1; dy <= 1; dy++) {
                    const unsigned* p = &g_grid[cp + dx * DXS + dy * DYS];
                    unsigned a = p[-1], b = p[0], c = p[1];
                    unsigned mx = a > b ? a : b;
                    mx = c > mx ? c : mx;
                    hmax = mx > hmax ? mx : hmax;
                }
            }
        }
        bool isPeak = valid && (hmax == sb);
        unsigned m = __ballot_sync(0xFFFFFFFFu, isPeak);
        int base = 0;
        if (lane == 0 && m) base = atomicAdd(&g_peak_count, __popc(m));
        base = __shfl_sync(0xFFFFFFFFu, base, 0);
        if (isPeak) {
            g_keys[base + __popc(m & ((1u << lane) - 1u))] = key;
            atomicAdd(&g_hist1[(sb >> 16) - BIN1_BASE], 1);
        }
    }
}

// ---------------- K3: single-level threshold (1 block, 512 thr) ----------------
__global__ void __launch_bounds__(NBIN1) k_thresh()
{
    __shared__ int csum[NBIN1];
    int t = threadIdx.x;
    int h = g_hist1[t];
    csum[t] = h;
    __syncthreads();
    for (int off = 1; off < NBIN1; off <<= 1) {
        int v = (t >= off) ? csum[t - off] : 0;
        __syncthreads();
        csum[t] += v;
        __syncthreads();
    }
    int total = csum[NBIN1 - 1];
    if (total < MAXP) {
        if (t == 0) g_thresh = 0u;      // take all peaks
        return;
    }
    int above = total - csum[t];        // strictly above bin t
    if (above < MAXP && above + h >= MAXP)
        g_thresh = ((unsigned)(t + BIN1_BASE)) << 16;
}

// ---------------- K4: compact survivors (grid-wide) ----------------
__global__ void __launch_bounds__(256) k_compact()
{
    int n = g_peak_count;
    unsigned th = g_thresh;
    int gsz = gridDim.x * blockDim.x;
    int idx = blockIdx.x * blockDim.x + threadIdx.x;
    int iters = (n + gsz - 1) / gsz;
    int lane = threadIdx.x & 31;
    for (int it = 0; it < iters; it++, idx += gsz) {
        bool take = false;
        unsigned long long key = 0ULL;
        if (idx < n) {
            key = g_keys[idx];
            take = ((unsigned)(key >> 32) >= th);
        }
        unsigned m = __ballot_sync(0xFFFFFFFFu, take);
        int base = 0;
        if (lane == 0 && m) base = atomicAdd(&g_ccount, __popc(m));
        base = __shfl_sync(0xFFFFFFFFu, base, 0);
        if (take) {
            int pos = base + __popc(m & ((1u << lane) - 1u));
            if (pos < CCAP) g_ckeys[pos] = key;
        }
    }
}

// ---------------- K5: sort 2048 + emit outputs (1 block, 1024 thr) ----------------
__global__ void __launch_bounds__(1024) k_sortout(float* __restrict__ out)
{
    __shared__ unsigned long long sk[CCAP];     // 16 KB
    __shared__ int fill[MAXP];
    __shared__ int sValid;
    int t = threadIdx.x;
    int M = g_ccount; if (M > CCAP) M = CCAP;
    sk[t]        = (t        < M) ? g_ckeys[t]        : 0ULL;
    sk[t + 1024] = (t + 1024 < M) ? g_ckeys[t + 1024] : 0ULL;
    __syncthreads();

    // bitonic sort, descending (2048 elems, 2/thread)
    for (int kk = 2; kk <= CCAP; kk <<= 1) {
        for (int j = kk >> 1; j > 0; j >>= 1) {
            #pragma unroll
            for (int half = 0; half < 2; half++) {
                int i = t + half * 1024;
                int ixj = i ^ j;
                if (ixj > i) {
                    unsigned long long a = sk[i], b = sk[ixj];
                    bool desc = ((i & kk) == 0);
                    if (desc ? (a < b) : (a > b)) { sk[i] = b; sk[ixj] = a; }
                }
            }
            __syncthreads();
        }
    }

    if (t == 0) {
        int valid = M < MAXP ? M : MAXP;
        sValid = valid;
        if (valid < MAXP) {   // practically never taken
            int need = MAXP - valid, got = 0;
            for (int i = 0; i < NPTS && got < need; i++) {
                bool isP = false;
                for (int q = 0; q < valid; q++) {
                    int pidx = (int)(~(unsigned)(sk[q] & 0xFFFFFFFFu));
                    if (pidx == i) { isP = true; break; }
                }
                if (!isP) { fill[valid + got] = i; got++; }
            }
        }
    }
    __syncthreads();

    if (t < MAXP) {
        int valid = sValid;
        float sc; int idx;
        if (t < valid) {
            unsigned long long key = sk[t];
            sc  = __uint_as_float((unsigned)(key >> 32));
            idx = (int)(~(unsigned)(key & 0xFFFFFFFFu));
        } else {
            sc  = -1.0f;
            idx = fill[t];
        }
        out[NPTS + t]        = (float)idx;
        out[NPTS + MAXP + t] = sc;
        int cell = g_cell[idx];
        float* pc = out + NPTS + 2 * MAXP + (size_t)t * 4;
        pc[0] = (float)(cell >> 24);
        pc[1] = (float)((cell >> 15) & 511);
        pc[2] = (float)((cell >> 6) & 511);
        pc[3] = (float)(cell & 63);
    }
}

// ---------------- launch ----------------
extern "C" void kernel_launch(void* const* d_in, const int* in_sizes, int n_in,
                              void* d_out, int out_size) {
    const float* feats = (const float*)d_in[0];
    const int*   cb    = (const int*)  d_in[1];
    const int*   cx    = (const int*)  d_in[2];
    const int*   cy    = (const int*)  d_in[3];
    const int*   cz    = (const int*)  d_in[4];
    const int*   mask  = (const int*)  d_in[5];
    const float* W1    = (const float*)d_in[6];
    const float* b1    = (const float*)d_in[7];
    const float* W2    = (const float*)d_in[8];
    const float* b2    = (const float*)d_in[9];
    float* out = (float*)d_out;

    // cleanup of PREVIOUS replay's state runs first; no-op on the very first call.
    k_clean_grid<<<2048, 256>>>();
    k_clean_hist<<<1, NBIN1>>>();
    k_reset<<<1, 32>>>();
    k_mlp<<<(NPTS + 255) / 256, 256>>>(feats, cb, cx, cy, cz, mask,
                                       W1, b1, W2, b2, out);   // 4th launch -> ncu
    k_peak<<<2048, 256>>>();
    k_thresh<<<1, NBIN1>>>();
    k_compact<<<512, 256>>>();
    k_sortout<<<1, 1024>>>(out);
}